// round 16
// baseline (speedup 1.0000x reference)
#include <cuda_runtime.h>
#include <cuda_fp16.h>
#include <math.h>
#include <stdint.h>

#define T_TOK 8192
#define H_DIM 1024
#define F_DIM 4096
#define E_NUM 8

// ---- scratch (static device globals; no allocation at launch time) ----
__device__ int      g_count[E_NUM];
__device__ int      g_tok[E_NUM * T_TOK];
__device__ float    g_gate[E_NUM * T_TOK];
__device__ __half   g_xh[(size_t)T_TOK * H_DIM];            // fp16 x
__device__ __half   g_w1h[(size_t)E_NUM * H_DIM * F_DIM];   // fp16 w1
__device__ __half   g_w2h[(size_t)E_NUM * F_DIM * H_DIM];   // fp16 w2
__device__ __half   g_hidden[(size_t)2 * T_TOK * F_DIM];    // fc1 out fp16

__device__ __forceinline__ void cp16(uint32_t dst, const void* src, uint32_t bytes) {
    asm volatile("cp.async.ca.shared.global [%0], [%1], 16, %2;"
                 :: "r"(dst), "l"(src), "r"(bytes) : "memory");
}
#define CP_COMMIT() asm volatile("cp.async.commit_group;" ::: "memory")
#define CP_WAIT(n)  asm volatile("cp.async.wait_group %0;" :: "n"(n) : "memory")

__device__ __forceinline__ void ldsm_x4(uint32_t* r, uint32_t addr) {
    asm volatile("ldmatrix.sync.aligned.m8n8.x4.shared.b16 {%0,%1,%2,%3}, [%4];"
                 : "=r"(r[0]), "=r"(r[1]), "=r"(r[2]), "=r"(r[3]) : "r"(addr));
}
__device__ __forceinline__ void ldsm_x4_t(uint32_t* r, uint32_t addr) {
    asm volatile("ldmatrix.sync.aligned.m8n8.x4.trans.shared.b16 {%0,%1,%2,%3}, [%4];"
                 : "=r"(r[0]), "=r"(r[1]), "=r"(r[2]), "=r"(r[3]) : "r"(addr));
}
__device__ __forceinline__ void mma_f16(float* c, const uint32_t* a, const uint32_t* b) {
    asm volatile(
        "mma.sync.aligned.m16n8k16.row.col.f32.f16.f16.f32 "
        "{%0,%1,%2,%3}, {%4,%5,%6,%7}, {%8,%9}, {%0,%1,%2,%3};"
        : "+f"(c[0]), "+f"(c[1]), "+f"(c[2]), "+f"(c[3])
        : "r"(a[0]), "r"(a[1]), "r"(a[2]), "r"(a[3]), "r"(b[0]), "r"(b[1]));
}

__device__ __forceinline__ float gelu_tanh(float v) {
    const float c = 0.7978845608028654f;
    float u = c * (v + 0.044715f * v * v * v);
    return 0.5f * v * (1.0f + tanhf(u));
}

// inline exclusive prefix over the 8 expert counts
__device__ __forceinline__ int expert_off(int e) {
    int off = 0;
#pragma unroll
    for (int k = 0; k < E_NUM; k++)
        if (k < e) off += g_count[k];
    return off;
}

// ======================= kernel 0: zero counts + output =====================
__global__ void zero_kernel(float4* __restrict__ out4, int n4) {
    if (blockIdx.x == 0 && threadIdx.x < E_NUM) g_count[threadIdx.x] = 0;
    int stride = gridDim.x * blockDim.x;
    float4 z = make_float4(0.f, 0.f, 0.f, 0.f);
    for (int i = blockIdx.x * blockDim.x + threadIdx.x; i < n4; i += stride)
        out4[i] = z;
}

// ======================= kernel 1: prep = router + weight cvt ===============
#define ROUTER_BLKS (T_TOK / 8)
__global__ void prep_kernel(const float* __restrict__ x, const float* __restrict__ rw,
                            const float* __restrict__ w1, const float* __restrict__ w2,
                            __half* __restrict__ xh,
                            __half* __restrict__ d1, __half* __restrict__ d2, int n8) {
    if (blockIdx.x >= ROUTER_BLKS) {
        int tid = threadIdx.y * 32 + threadIdx.x;
        int i = (blockIdx.x - ROUTER_BLKS) * 256 + tid;
        const float* s; __half* d; int j = i;
        if (i < n8) { s = w1; d = d1; }
        else if (i < 2 * n8) { s = w2; d = d2; j = i - n8; }
        else return;
        float4 a = ((const float4*)s)[2 * j];
        float4 b = ((const float4*)s)[2 * j + 1];
        __half2 h[4];
        h[0] = __floats2half2_rn(a.x, a.y);
        h[1] = __floats2half2_rn(a.z, a.w);
        h[2] = __floats2half2_rn(b.x, b.y);
        h[3] = __floats2half2_rn(b.z, b.w);
        ((uint4*)d)[j] = *(uint4*)h;
        return;
    }
    int t = blockIdx.x * 8 + threadIdx.y;
    int lane = threadIdx.x;
    float acc[E_NUM];
#pragma unroll
    for (int e = 0; e < E_NUM; e++) acc[e] = 0.0f;
    const float* xrow = x + (size_t)t * H_DIM;
    __half* xhrow = xh + (size_t)t * H_DIM;
    for (int h = lane; h < H_DIM; h += 32) {
        float xv = xrow[h];
        xhrow[h] = __float2half_rn(xv);
        const float4* r = (const float4*)(rw + (size_t)h * E_NUM);
        float4 r0 = r[0], r1 = r[1];
        acc[0] += xv * r0.x; acc[1] += xv * r0.y;
        acc[2] += xv * r0.z; acc[3] += xv * r0.w;
        acc[4] += xv * r1.x; acc[5] += xv * r1.y;
        acc[6] += xv * r1.z; acc[7] += xv * r1.w;
    }
#pragma unroll
    for (int e = 0; e < E_NUM; e++) {
#pragma unroll
        for (int off = 16; off > 0; off >>= 1)
            acc[e] += __shfl_xor_sync(0xffffffffu, acc[e], off);
    }
    if (lane == 0) {
        float m = acc[0];
#pragma unroll
        for (int e = 1; e < E_NUM; e++) m = fmaxf(m, acc[e]);
        float p[E_NUM]; float s = 0.0f;
#pragma unroll
        for (int e = 0; e < E_NUM; e++) { p[e] = expf(acc[e] - m); s += p[e]; }
        float inv = 1.0f / s;
        int i1 = 0; float v1 = p[0];
#pragma unroll
        for (int e = 1; e < E_NUM; e++) if (p[e] > v1) { v1 = p[e]; i1 = e; }
        int i2 = -1; float v2 = -1.0f;
#pragma unroll
        for (int e = 0; e < E_NUM; e++) if (e != i1 && p[e] > v2) { v2 = p[e]; i2 = e; }
        int s1 = atomicAdd(&g_count[i1], 1);
        g_tok[i1 * T_TOK + s1]  = t;
        g_gate[i1 * T_TOK + s1] = v1 * inv;
        int s2 = atomicAdd(&g_count[i2], 1);
        g_tok[i2 * T_TOK + s2]  = t;
        g_gate[i2 * T_TOK + s2] = v2 * inv;
    }
}

// ======================= fc1: unchanged (R9 config) =========================
#define NSTAGE    4
#define A_PITCH   48u
#define A_STRIDE  6144u
#define B1_PITCH  528u
#define B1_STRIDE 8448u
#define B1_OFF    (NSTAGE * A_STRIDE)              // 24576
#define SMEM1     (B1_OFF + NSTAGE * B1_STRIDE)    // 58368

__global__ void __launch_bounds__(256, 1)
fc1_gemm(const __half* __restrict__ Asrc, const __half* __restrict__ W)
{
    extern __shared__ char sm[];
    const int e = blockIdx.z;
    const int n = g_count[e];
    const int row0 = blockIdx.y * 128;
    if (row0 >= n) return;
    const int col0 = blockIdx.x * 256;

    const uint32_t sbase = (uint32_t)__cvta_generic_to_shared(sm);
    const int tid = threadIdx.x;
    const int lane = tid & 31;
    const int w = tid >> 5;
    const int wm = w & 1;
    const int wn = w >> 1;

    const int am = tid >> 1;
    const int ah = (tid & 1) * 8;
    const __half* aptr = Asrc;
    uint32_t abytes = 0;
    if (row0 + am < n) {
        abytes = 16;
        aptr = Asrc + (size_t)g_tok[e * T_TOK + row0 + am] * H_DIM + ah;
    }
    const int bk = tid >> 4;
    const int bh = (tid & 15) * 16;
    const __half* bptr = W + (size_t)e * H_DIM * F_DIM + (size_t)bk * F_DIM + col0 + bh;

    const uint32_t dA = sbase + (uint32_t)am * A_PITCH + (uint32_t)(tid & 1) * 16u;
    const uint32_t dB = sbase + B1_OFF + (uint32_t)bk * B1_PITCH + (uint32_t)(tid & 15) * 32u;

    auto issue = [&](int s) {
        int st = s & (NSTAGE - 1);
        cp16(dA + (uint32_t)st * A_STRIDE, aptr + (size_t)s * 16, abytes);
        uint32_t db = dB + (uint32_t)st * B1_STRIDE;
        const __half* bp = bptr + (size_t)s * 16 * F_DIM;
        cp16(db,      bp,     16);
        cp16(db + 16, bp + 8, 16);
    };

    float acc[4][8][4];
#pragma unroll
    for (int i = 0; i < 4; i++)
#pragma unroll
        for (int j = 0; j < 8; j++)
#pragma unroll
            for (int q = 0; q < 4; q++) acc[i][j][q] = 0.0f;

    const uint32_t aoff = (uint32_t)(((lane & 7) + ((lane >> 3) & 1) * 8) * A_PITCH
                                     + (lane >> 4) * 16);
    const uint32_t boff = (uint32_t)((lane & 15) * B1_PITCH + (lane >> 4) * 16);

    auto compute = [&](int st) {
        const uint32_t sA = sbase + (uint32_t)st * A_STRIDE + aoff;
        const uint32_t sB = sbase + B1_OFF + (uint32_t)st * B1_STRIDE + boff;
        uint32_t af[4][4], bf[4][4];
#pragma unroll
        for (int mf = 0; mf < 4; mf++)
            ldsm_x4(af[mf], sA + (uint32_t)(wm * 64 + mf * 16) * A_PITCH);
#pragma unroll
        for (int p = 0; p < 4; p++)
            ldsm_x4_t(bf[p], sB + (uint32_t)(wn * 128 + p * 32));
#pragma unroll
        for (int mf = 0; mf < 4; mf++)
#pragma unroll
            for (int p = 0; p < 4; p++) {
                mma_f16(acc[mf][2 * p],     af[mf], bf[p]);
                mma_f16(acc[mf][2 * p + 1], af[mf], bf[p] + 2);
            }
    };

    constexpr int S = H_DIM / 16;
    issue(0); CP_COMMIT();
    issue(1); CP_COMMIT();
    issue(2); CP_COMMIT();
#pragma unroll 1
    for (int s = 0; s < S; s++) {
        CP_WAIT(2);
        __syncthreads();
        if (s + 3 < S) issue(s + 3);
        CP_COMMIT();
        compute(s & (NSTAGE - 1));
    }

    const int gq = lane >> 2;
    const int kq4 = lane & 3;
    const int hrow0 = expert_off(e);
#pragma unroll
    for (int mf = 0; mf < 4; mf++) {
        int rlo = row0 + wm * 64 + mf * 16 + gq;
        int rhi = rlo + 8;
        __half* dlo = g_hidden + (size_t)(hrow0 + rlo) * F_DIM;
        __half* dhi = g_hidden + (size_t)(hrow0 + rhi) * F_DIM;
#pragma unroll
        for (int nf = 0; nf < 8; nf++) {
            int c = col0 + wn * 64 + nf * 8 + 2 * kq4;
            if (rlo < n) {
                __half2 v = __floats2half2_rn(gelu_tanh(acc[mf][nf][0]),
                                              gelu_tanh(acc[mf][nf][1]));
                *(__half2*)(dlo + c) = v;
            }
            if (rhi < n) {
                __half2 v = __floats2half2_rn(gelu_tanh(acc[mf][nf][2]),
                                              gelu_tanh(acc[mf][nf][3]));
                *(__half2*)(dhi + c) = v;
            }
        }
    }
}

// ======================= fc2: 128x128 tile, 4 warps, warp tile 64x64 ========
// 128 threads (2Mx2N warps), 2 CTAs/SM, atomic combine epilogue.
#define B2_PITCH  272u
#define B2_STRIDE 4352u                            // 16*272
#define B2_OFF    (NSTAGE * A_STRIDE)              // 24576
#define SMEM2     (B2_OFF + NSTAGE * B2_STRIDE)    // 41984

__global__ void __launch_bounds__(128, 2)
fc2_gemm(const __half* __restrict__ Asrc, const __half* __restrict__ W,
         float* __restrict__ Out)
{
    extern __shared__ char sm[];
    const int e = blockIdx.z;
    const int n = g_count[e];
    const int row0 = blockIdx.y * 128;
    if (row0 >= n) return;
    const int col0 = blockIdx.x * 128;

    const uint32_t sbase = (uint32_t)__cvta_generic_to_shared(sm);
    const int tid = threadIdx.x;
    const int lane = tid & 31;
    const int w = tid >> 5;          // 0..3
    const int wm = w & 1;            // 2 M warps (64 rows each)
    const int wn = w >> 1;           // 2 N warps (64 cols each)

    const int yoff = expert_off(e);
    // A: 1 thread per row (128 rows), 2x16B chunks per stage
    const __half* aptr = Asrc;
    uint32_t abytes = 0;
    if (row0 + tid < n) {
        abytes = 16;
        aptr = Asrc + (size_t)(yoff + row0 + tid) * F_DIM;
    }
    // B: 16 k-rows x 8 threads/row, 32B per thread (contiguous, coalesced)
    const int bk = tid >> 3;
    const __half* bptr = W + (size_t)e * F_DIM * H_DIM + (size_t)bk * H_DIM
                         + col0 + (tid & 7) * 16;

    const uint32_t dA = sbase + (uint32_t)tid * A_PITCH;
    const uint32_t dB = sbase + B2_OFF + (uint32_t)bk * B2_PITCH + (uint32_t)(tid & 7) * 32u;

    auto issue = [&](int s) {
        int st = s & (NSTAGE - 1);
        uint32_t da = dA + (uint32_t)st * A_STRIDE;
        const __half* ap = aptr + (size_t)s * 16;
        cp16(da,      ap,     abytes);
        cp16(da + 16, ap + 8, abytes);
        uint32_t db = dB + (uint32_t)st * B2_STRIDE;
        const __half* bp = bptr + (size_t)s * 16 * H_DIM;
        cp16(db,      bp,     16);
        cp16(db + 16, bp + 8, 16);
    };

    float acc[4][8][4];
#pragma unroll
    for (int i = 0; i < 4; i++)
#pragma unroll
        for (int j = 0; j < 8; j++)
#pragma unroll
            for (int q = 0; q < 4; q++) acc[i][j][q] = 0.0f;

    const uint32_t aoff = (uint32_t)(((lane & 7) + ((lane >> 3) & 1) * 8) * A_PITCH
                                     + (lane >> 4) * 16);
    const uint32_t boff = (uint32_t)((lane & 15) * B2_PITCH + (lane >> 4) * 16);

    auto compute = [&](int st) {
        const uint32_t sA = sbase + (uint32_t)st * A_STRIDE + aoff;
        const uint32_t sB = sbase + B2_OFF + (uint32_t)st * B2_STRIDE + boff;
        uint32_t af[4][4], bf[4][4];
#pragma unroll
        for (int mf = 0; mf < 4; mf++)
            ldsm_x4(af[mf], sA + (uint32_t)(wm * 64 + mf * 16) * A_PITCH);
#pragma unroll
        for (int p = 0; p < 4; p++)
            ldsm_x4_t(bf[p], sB + (uint32_t)(wn * 128 + p * 32));
#pragma unroll
        for (int mf = 0; mf < 4; mf++)
#pragma unroll
            for (int p = 0; p < 4; p++) {
                mma_f16(acc[mf][2 * p],     af[mf], bf[p]);
                mma_f16(acc[mf][2 * p + 1], af[mf], bf[p] + 2);
            }
    };

    constexpr int S = F_DIM / 16;
    issue(0); CP_COMMIT();
    issue(1); CP_COMMIT();
    issue(2); CP_COMMIT();
#pragma unroll 1
    for (int s = 0; s < S; s++) {
        CP_WAIT(2);
        __syncthreads();
        if (s + 3 < S) issue(s + 3);
        CP_COMMIT();
        compute(s & (NSTAGE - 1));
    }

    // ---- epilogue: gate-weighted atomic combine into out ----
    const int gq = lane >> 2;
    const int kq4 = lane & 3;
#pragma unroll
    for (int mf = 0; mf < 4; mf++) {
        int rlo = row0 + wm * 64 + mf * 16 + gq;
        int rhi = rlo + 8;
        int tok_lo = 0, tok_hi = 0; float gl = 0.f, gh = 0.f;
        if (rlo < n) { tok_lo = g_tok[e * T_TOK + rlo]; gl = g_gate[e * T_TOK + rlo]; }
        if (rhi < n) { tok_hi = g_tok[e * T_TOK + rhi]; gh = g_gate[e * T_TOK + rhi]; }
        float* olo = Out + (size_t)tok_lo * H_DIM;
        float* ohi = Out + (size_t)tok_hi * H_DIM;
#pragma unroll
        for (int nf = 0; nf < 8; nf++) {
            int c = col0 + wn * 64 + nf * 8 + 2 * kq4;
            if (rlo < n) {
                atomicAdd(olo + c,     gl * acc[mf][nf][0]);
                atomicAdd(olo + c + 1, gl * acc[mf][nf][1]);
            }
            if (rhi < n) {
                atomicAdd(ohi + c,     gh * acc[mf][nf][2]);
                atomicAdd(ohi + c + 1, gh * acc[mf][nf][3]);
            }
        }
    }
}

// ======================= launch =======================
extern "C" void kernel_launch(void* const* d_in, const int* in_sizes, int n_in,
                              void* d_out, int out_size) {
    const float* x  = (const float*)d_in[0];
    const float* rw = (const float*)d_in[1];
    const float* w1 = (const float*)d_in[2];
    const float* w2 = (const float*)d_in[3];
    float* out = (float*)d_out;

    cudaFuncSetAttribute(fc1_gemm, cudaFuncAttributeMaxDynamicSharedMemorySize, SMEM1);
    cudaFuncSetAttribute(fc2_gemm, cudaFuncAttributeMaxDynamicSharedMemorySize, SMEM2);

    __half* xh  = nullptr; cudaGetSymbolAddress((void**)&xh,  g_xh);
    __half* w1h = nullptr; cudaGetSymbolAddress((void**)&w1h, g_w1h);
    __half* w2h = nullptr; cudaGetSymbolAddress((void**)&w2h, g_w2h);
    __half* hid = nullptr; cudaGetSymbolAddress((void**)&hid, g_hidden);

    const int wcount8 = E_NUM * H_DIM * F_DIM / 8;
    const int cvt_blks = (2 * wcount8 + 255) / 256;

    zero_kernel<<<2048, 256>>>((float4*)out, out_size / 4);
    prep_kernel<<<ROUTER_BLKS + cvt_blks, dim3(32, 8)>>>(x, rw, w1, w2, xh, w1h, w2h, wcount8);
    fc1_gemm<<<dim3(F_DIM / 256, T_TOK / 128, E_NUM), 256, SMEM1>>>(xh, w1h);
    fc2_gemm<<<dim3(H_DIM / 128, T_TOK / 128, E_NUM), 128, SMEM2>>>(hid, w2h, out);
}

// round 17
// speedup vs baseline: 1.1604x; 1.1604x over previous
#include <cuda_runtime.h>
#include <cuda_fp16.h>
#include <math.h>
#include <stdint.h>

#define T_TOK 8192
#define H_DIM 1024
#define F_DIM 4096
#define E_NUM 8

// ---- scratch (static device globals; no allocation at launch time) ----
__device__ int      g_count[E_NUM];
__device__ int      g_tok[E_NUM * T_TOK];
__device__ float    g_gate[E_NUM * T_TOK];
__device__ __half   g_xh[(size_t)T_TOK * H_DIM];            // fp16 x
__device__ __half   g_w1h[(size_t)E_NUM * H_DIM * F_DIM];   // fp16 w1
__device__ __half   g_w2h[(size_t)E_NUM * F_DIM * H_DIM];   // fp16 w2
__device__ __half   g_hidden[(size_t)2 * T_TOK * F_DIM];    // fc1 out fp16

__device__ __forceinline__ void cp16(uint32_t dst, const void* src, uint32_t bytes) {
    asm volatile("cp.async.ca.shared.global [%0], [%1], 16, %2;"
                 :: "r"(dst), "l"(src), "r"(bytes) : "memory");
}
#define CP_COMMIT() asm volatile("cp.async.commit_group;" ::: "memory")
#define CP_WAIT(n)  asm volatile("cp.async.wait_group %0;" :: "n"(n) : "memory")

__device__ __forceinline__ void ldsm_x4(uint32_t* r, uint32_t addr) {
    asm volatile("ldmatrix.sync.aligned.m8n8.x4.shared.b16 {%0,%1,%2,%3}, [%4];"
                 : "=r"(r[0]), "=r"(r[1]), "=r"(r[2]), "=r"(r[3]) : "r"(addr));
}
__device__ __forceinline__ void ldsm_x4_t(uint32_t* r, uint32_t addr) {
    asm volatile("ldmatrix.sync.aligned.m8n8.x4.trans.shared.b16 {%0,%1,%2,%3}, [%4];"
                 : "=r"(r[0]), "=r"(r[1]), "=r"(r[2]), "=r"(r[3]) : "r"(addr));
}
__device__ __forceinline__ void mma_f16(float* c, const uint32_t* a, const uint32_t* b) {
    asm volatile(
        "mma.sync.aligned.m16n8k16.row.col.f32.f16.f16.f32 "
        "{%0,%1,%2,%3}, {%4,%5,%6,%7}, {%8,%9}, {%0,%1,%2,%3};"
        : "+f"(c[0]), "+f"(c[1]), "+f"(c[2]), "+f"(c[3])
        : "r"(a[0]), "r"(a[1]), "r"(a[2]), "r"(a[3]), "r"(b[0]), "r"(b[1]));
}

__device__ __forceinline__ float gelu_tanh(float v) {
    const float c = 0.7978845608028654f;
    float u = c * (v + 0.044715f * v * v * v);
    return 0.5f * v * (1.0f + tanhf(u));
}

// inline exclusive prefix over the 8 expert counts
__device__ __forceinline__ int expert_off(int e) {
    int off = 0;
#pragma unroll
    for (int k = 0; k < E_NUM; k++)
        if (k < e) off += g_count[k];
    return off;
}

// ======================= kernel 0: zero counts + output =====================
__global__ void zero_kernel(float4* __restrict__ out4, int n4) {
    if (blockIdx.x == 0 && threadIdx.x < E_NUM) g_count[threadIdx.x] = 0;
    int stride = gridDim.x * blockDim.x;
    float4 z = make_float4(0.f, 0.f, 0.f, 0.f);
    for (int i = blockIdx.x * blockDim.x + threadIdx.x; i < n4; i += stride)
        out4[i] = z;
}

// ======================= kernel 1: prep = router + weight cvt ===============
#define ROUTER_BLKS (T_TOK / 8)
__global__ void prep_kernel(const float* __restrict__ x, const float* __restrict__ rw,
                            const float* __restrict__ w1, const float* __restrict__ w2,
                            __half* __restrict__ xh,
                            __half* __restrict__ d1, __half* __restrict__ d2, int n8) {
    if (blockIdx.x >= ROUTER_BLKS) {
        int tid = threadIdx.y * 32 + threadIdx.x;
        int i = (blockIdx.x - ROUTER_BLKS) * 256 + tid;
        const float* s; __half* d; int j = i;
        if (i < n8) { s = w1; d = d1; }
        else if (i < 2 * n8) { s = w2; d = d2; j = i - n8; }
        else return;
        float4 a = ((const float4*)s)[2 * j];
        float4 b = ((const float4*)s)[2 * j + 1];
        __half2 h[4];
        h[0] = __floats2half2_rn(a.x, a.y);
        h[1] = __floats2half2_rn(a.z, a.w);
        h[2] = __floats2half2_rn(b.x, b.y);
        h[3] = __floats2half2_rn(b.z, b.w);
        ((uint4*)d)[j] = *(uint4*)h;
        return;
    }
    int t = blockIdx.x * 8 + threadIdx.y;
    int lane = threadIdx.x;
    float acc[E_NUM];
#pragma unroll
    for (int e = 0; e < E_NUM; e++) acc[e] = 0.0f;
    const float* xrow = x + (size_t)t * H_DIM;
    __half* xhrow = xh + (size_t)t * H_DIM;
    for (int h = lane; h < H_DIM; h += 32) {
        float xv = xrow[h];
        xhrow[h] = __float2half_rn(xv);
        const float4* r = (const float4*)(rw + (size_t)h * E_NUM);
        float4 r0 = r[0], r1 = r[1];
        acc[0] += xv * r0.x; acc[1] += xv * r0.y;
        acc[2] += xv * r0.z; acc[3] += xv * r0.w;
        acc[4] += xv * r1.x; acc[5] += xv * r1.y;
        acc[6] += xv * r1.z; acc[7] += xv * r1.w;
    }
#pragma unroll
    for (int e = 0; e < E_NUM; e++) {
#pragma unroll
        for (int off = 16; off > 0; off >>= 1)
            acc[e] += __shfl_xor_sync(0xffffffffu, acc[e], off);
    }
    if (lane == 0) {
        float m = acc[0];
#pragma unroll
        for (int e = 1; e < E_NUM; e++) m = fmaxf(m, acc[e]);
        float p[E_NUM]; float s = 0.0f;
#pragma unroll
        for (int e = 0; e < E_NUM; e++) { p[e] = expf(acc[e] - m); s += p[e]; }
        float inv = 1.0f / s;
        int i1 = 0; float v1 = p[0];
#pragma unroll
        for (int e = 1; e < E_NUM; e++) if (p[e] > v1) { v1 = p[e]; i1 = e; }
        int i2 = -1; float v2 = -1.0f;
#pragma unroll
        for (int e = 0; e < E_NUM; e++) if (e != i1 && p[e] > v2) { v2 = p[e]; i2 = e; }
        int s1 = atomicAdd(&g_count[i1], 1);
        g_tok[i1 * T_TOK + s1]  = t;
        g_gate[i1 * T_TOK + s1] = v1 * inv;
        int s2 = atomicAdd(&g_count[i2], 1);
        g_tok[i2 * T_TOK + s2]  = t;
        g_gate[i2 * T_TOK + s2] = v2 * inv;
    }
}

// ======================= shared GEMM geometry ===============================
// 128x128 tile, BK=16, 256 threads (8 warps 2Mx4N), warp tile 64x32,
// 2 CTAs/SM (16 warps resident — the measured-best latency-hiding point).
#define NSTAGE   4
#define A_PITCH  48u
#define A_STRIDE 6144u                            // 128*48
#define B_PITCH  272u
#define B_STRIDE 4352u                            // 16*272
#define B_OFF    (NSTAGE * A_STRIDE)              // 24576
#define SMEM_GB  (B_OFF + NSTAGE * B_STRIDE)      // 41984

// ======================= fc1: 128x128, 2 CTAs/SM, gelu epilogue =============
__global__ void __launch_bounds__(256, 2)
fc1_gemm(const __half* __restrict__ Asrc, const __half* __restrict__ W)
{
    extern __shared__ char sm[];
    const int e = blockIdx.z;
    const int n = g_count[e];
    const int row0 = blockIdx.y * 128;
    if (row0 >= n) return;
    const int col0 = blockIdx.x * 128;

    const uint32_t sbase = (uint32_t)__cvta_generic_to_shared(sm);
    const int tid = threadIdx.x;
    const int lane = tid & 31;
    const int w = tid >> 5;
    const int wm = w & 1;
    const int wn = w >> 1;

    const int am = tid >> 1;
    const int ah = (tid & 1) * 8;
    const __half* aptr = Asrc;
    uint32_t abytes = 0;
    if (row0 + am < n) {
        abytes = 16;
        aptr = Asrc + (size_t)g_tok[e * T_TOK + row0 + am] * H_DIM + ah;
    }
    const int bk = tid >> 4;
    const int bh = (tid & 15) * 8;
    const __half* bptr = W + (size_t)e * H_DIM * F_DIM + (size_t)bk * F_DIM + col0 + bh;

    const uint32_t dA = sbase + (uint32_t)am * A_PITCH + (uint32_t)(tid & 1) * 16u;
    const uint32_t dB = sbase + B_OFF + (uint32_t)bk * B_PITCH + (uint32_t)(tid & 15) * 16u;

    auto issue = [&](int s) {
        int st = s & (NSTAGE - 1);
        cp16(dA + (uint32_t)st * A_STRIDE, aptr + (size_t)s * 16, abytes);
        cp16(dB + (uint32_t)st * B_STRIDE, bptr + (size_t)s * 16 * F_DIM, 16);
    };

    float acc[4][4][4];
#pragma unroll
    for (int i = 0; i < 4; i++)
#pragma unroll
        for (int j = 0; j < 4; j++)
#pragma unroll
            for (int q = 0; q < 4; q++) acc[i][j][q] = 0.0f;

    const uint32_t aoff = (uint32_t)(((lane & 7) + ((lane >> 3) & 1) * 8) * A_PITCH
                                     + (lane >> 4) * 16);
    const uint32_t boff = (uint32_t)((lane & 15) * B_PITCH + (lane >> 4) * 16);

    auto compute = [&](int st) {
        const uint32_t sA = sbase + (uint32_t)st * A_STRIDE + aoff;
        const uint32_t sB = sbase + B_OFF + (uint32_t)st * B_STRIDE + boff;
        uint32_t af[4][4], bf[2][4];
#pragma unroll
        for (int mf = 0; mf < 4; mf++)
            ldsm_x4(af[mf], sA + (uint32_t)(wm * 64 + mf * 16) * A_PITCH);
#pragma unroll
        for (int p = 0; p < 2; p++)
            ldsm_x4_t(bf[p], sB + (uint32_t)(wn * 64 + p * 32));
#pragma unroll
        for (int mf = 0; mf < 4; mf++)
#pragma unroll
            for (int p = 0; p < 2; p++) {
                mma_f16(acc[mf][2 * p],     af[mf], bf[p]);
                mma_f16(acc[mf][2 * p + 1], af[mf], bf[p] + 2);
            }
    };

    constexpr int S = H_DIM / 16;
    issue(0); CP_COMMIT();
    issue(1); CP_COMMIT();
    issue(2); CP_COMMIT();
#pragma unroll 1
    for (int s = 0; s < S; s++) {
        CP_WAIT(2);
        __syncthreads();
        if (s + 3 < S) issue(s + 3);
        CP_COMMIT();
        compute(s & (NSTAGE - 1));
    }

    const int gq = lane >> 2;
    const int kq4 = lane & 3;
    const int hrow0 = expert_off(e);
#pragma unroll
    for (int mf = 0; mf < 4; mf++) {
        int rlo = row0 + wm * 64 + mf * 16 + gq;
        int rhi = rlo + 8;
        __half* dlo = g_hidden + (size_t)(hrow0 + rlo) * F_DIM;
        __half* dhi = g_hidden + (size_t)(hrow0 + rhi) * F_DIM;
#pragma unroll
        for (int nf = 0; nf < 4; nf++) {
            int c = col0 + wn * 32 + nf * 8 + 2 * kq4;
            if (rlo < n) {
                __half2 v = __floats2half2_rn(gelu_tanh(acc[mf][nf][0]),
                                              gelu_tanh(acc[mf][nf][1]));
                *(__half2*)(dlo + c) = v;
            }
            if (rhi < n) {
                __half2 v = __floats2half2_rn(gelu_tanh(acc[mf][nf][2]),
                                              gelu_tanh(acc[mf][nf][3]));
                *(__half2*)(dhi + c) = v;
            }
        }
    }
}

// ======================= fc2: 128x128, 2 CTAs/SM, atomic combine ============
__global__ void __launch_bounds__(256, 2)
fc2_gemm(const __half* __restrict__ Asrc, const __half* __restrict__ W,
         float* __restrict__ Out)
{
    extern __shared__ char sm[];
    const int e = blockIdx.z;
    const int n = g_count[e];
    const int row0 = blockIdx.y * 128;
    if (row0 >= n) return;
    const int col0 = blockIdx.x * 128;

    const uint32_t sbase = (uint32_t)__cvta_generic_to_shared(sm);
    const int tid = threadIdx.x;
    const int lane = tid & 31;
    const int w = tid >> 5;
    const int wm = w & 1;
    const int wn = w >> 1;

    const int yoff = expert_off(e);
    const int am = tid >> 1;
    const int ah = (tid & 1) * 8;
    const __half* aptr = Asrc;
    uint32_t abytes = 0;
    if (row0 + am < n) {
        abytes = 16;
        aptr = Asrc + (size_t)(yoff + row0 + am) * F_DIM + ah;
    }
    const int bk = tid >> 4;
    const int bh = (tid & 15) * 8;
    const __half* bptr = W + (size_t)e * F_DIM * H_DIM + (size_t)bk * H_DIM + col0 + bh;

    const uint32_t dA = sbase + (uint32_t)am * A_PITCH + (uint32_t)(tid & 1) * 16u;
    const uint32_t dB = sbase + B_OFF + (uint32_t)bk * B_PITCH + (uint32_t)(tid & 15) * 16u;

    auto issue = [&](int s) {
        int st = s & (NSTAGE - 1);
        cp16(dA + (uint32_t)st * A_STRIDE, aptr + (size_t)s * 16, abytes);
        cp16(dB + (uint32_t)st * B_STRIDE, bptr + (size_t)s * 16 * H_DIM, 16);
    };

    float acc[4][4][4];
#pragma unroll
    for (int i = 0; i < 4; i++)
#pragma unroll
        for (int j = 0; j < 4; j++)
#pragma unroll
            for (int q = 0; q < 4; q++) acc[i][j][q] = 0.0f;

    const uint32_t aoff = (uint32_t)(((lane & 7) + ((lane >> 3) & 1) * 8) * A_PITCH
                                     + (lane >> 4) * 16);
    const uint32_t boff = (uint32_t)((lane & 15) * B_PITCH + (lane >> 4) * 16);

    auto compute = [&](int st) {
        const uint32_t sA = sbase + (uint32_t)st * A_STRIDE + aoff;
        const uint32_t sB = sbase + B_OFF + (uint32_t)st * B_STRIDE + boff;
        uint32_t af[4][4], bf[2][4];
#pragma unroll
        for (int mf = 0; mf < 4; mf++)
            ldsm_x4(af[mf], sA + (uint32_t)(wm * 64 + mf * 16) * A_PITCH);
#pragma unroll
        for (int p = 0; p < 2; p++)
            ldsm_x4_t(bf[p], sB + (uint32_t)(wn * 64 + p * 32));
#pragma unroll
        for (int mf = 0; mf < 4; mf++)
#pragma unroll
            for (int p = 0; p < 2; p++) {
                mma_f16(acc[mf][2 * p],     af[mf], bf[p]);
                mma_f16(acc[mf][2 * p + 1], af[mf], bf[p] + 2);
            }
    };

    constexpr int S = F_DIM / 16;
    issue(0); CP_COMMIT();
    issue(1); CP_COMMIT();
    issue(2); CP_COMMIT();
#pragma unroll 1
    for (int s = 0; s < S; s++) {
        CP_WAIT(2);
        __syncthreads();
        if (s + 3 < S) issue(s + 3);
        CP_COMMIT();
        compute(s & (NSTAGE - 1));
    }

    // ---- epilogue: gate-weighted atomic combine into out ----
    const int gq = lane >> 2;
    const int kq4 = lane & 3;
#pragma unroll
    for (int mf = 0; mf < 4; mf++) {
        int rlo = row0 + wm * 64 + mf * 16 + gq;
        int rhi = rlo + 8;
        int tok_lo = 0, tok_hi = 0; float gl = 0.f, gh = 0.f;
        if (rlo < n) { tok_lo = g_tok[e * T_TOK + rlo]; gl = g_gate[e * T_TOK + rlo]; }
        if (rhi < n) { tok_hi = g_tok[e * T_TOK + rhi]; gh = g_gate[e * T_TOK + rhi]; }
        float* olo = Out + (size_t)tok_lo * H_DIM;
        float* ohi = Out + (size_t)tok_hi * H_DIM;
#pragma unroll
        for (int nf = 0; nf < 4; nf++) {
            int c = col0 + wn * 32 + nf * 8 + 2 * kq4;
            if (rlo < n) {
                atomicAdd(olo + c,     gl * acc[mf][nf][0]);
                atomicAdd(olo + c + 1, gl * acc[mf][nf][1]);
            }
            if (rhi < n) {
                atomicAdd(ohi + c,     gh * acc[mf][nf][2]);
                atomicAdd(ohi + c + 1, gh * acc[mf][nf][3]);
            }
        }
    }
}

// ======================= launch =======================
extern "C" void kernel_launch(void* const* d_in, const int* in_sizes, int n_in,
                              void* d_out, int out_size) {
    const float* x  = (const float*)d_in[0];
    const float* rw = (const float*)d_in[1];
    const float* w1 = (const float*)d_in[2];
    const float* w2 = (const float*)d_in[3];
    float* out = (float*)d_out;

    cudaFuncSetAttribute(fc1_gemm, cudaFuncAttributeMaxDynamicSharedMemorySize, SMEM_GB);
    cudaFuncSetAttribute(fc2_gemm, cudaFuncAttributeMaxDynamicSharedMemorySize, SMEM_GB);

    __half* xh  = nullptr; cudaGetSymbolAddress((void**)&xh,  g_xh);
    __half* w1h = nullptr; cudaGetSymbolAddress((void**)&w1h, g_w1h);
    __half* w2h = nullptr; cudaGetSymbolAddress((void**)&w2h, g_w2h);
    __half* hid = nullptr; cudaGetSymbolAddress((void**)&hid, g_hidden);

    const int wcount8 = E_NUM * H_DIM * F_DIM / 8;
    const int cvt_blks = (2 * wcount8 + 255) / 256;

    zero_kernel<<<2048, 256>>>((float4*)out, out_size / 4);
    prep_kernel<<<ROUTER_BLKS + cvt_blks, dim3(32, 8)>>>(x, rw, w1, w2, xh, w1h, w2h, wcount8);
    fc1_gemm<<<dim3(F_DIM / 128, T_TOK / 128, E_NUM), 256, SMEM_GB>>>(xh, w1h);
    fc2_gemm<<<dim3(H_DIM / 128, T_TOK / 128, E_NUM), 256, SMEM_GB>>>(hid, w2h, out);
}